// round 8
// baseline (speedup 1.0000x reference)
#include <cuda_runtime.h>
#include <cuda_fp16.h>
#include <cstdint>
#include <cstddef>

#define NN 100000
#define NE 1600000
#define FD 128
#define NC 10
#define RP 12          // fp32 z-row stride: 10 feats + scalar + dis (48B)
#define AP 16          // accumulator row stride (64B aligned)
#define HP 16          // fp16 mirror row stride in halves (32B aligned)
#define NG 64
#define NB_N 391       // ceil(NN/256)

// ---------------- device scratch (allocation-free rule) ----------------
__device__ __align__(128) float  g_z0[(size_t)NN * RP];   // dr*y0, s10=dr
__device__ __align__(128) __half g_z0h[(size_t)NN * HP];  // fp16 mirror of z0
__device__ __align__(128) float  g_a1[(size_t)NN * AP];   // edge acc pass 1
__device__ __align__(128) float  g_z1[(size_t)NN * RP];   // s10=t10*s2, s11=dc
__device__ __align__(128) __half g_z1h[(size_t)NN * HP];  // fp16 mirror of z1
__device__ __align__(128) float  g_a2[(size_t)NN * AP];   // edge acc pass 2
__device__ int2  g_edges[NE];
__device__ float g_u[NN];
__device__ int   g_deg[NN];       // in-degree (self-loop as +1 at use)
__device__ float g_W12[FD * RP];
__device__ float g_c1[NC];
__device__ float g_pool[NG * NC];
__device__ float g_pu[NG];
__device__ float g_pv[NG];
__device__ int   g_cnt[NG];
__device__ int   g_is64;

// ---------------- helpers ----------------
__device__ __forceinline__ int ld_idx(const void* p, long long i, int is64) {
    if (is64) return (int)((const long long*)p)[i];
    return ((const int*)p)[i];
}
__device__ __forceinline__ void red_add_v4(float* p, float4 v) {
    asm volatile("red.global.add.v4.f32 [%0], {%1,%2,%3,%4};"
                 :: "l"(p), "f"(v.x), "f"(v.y), "f"(v.z), "f"(v.w)
                 : "memory");
}
__device__ __forceinline__ unsigned h2u(float a, float b) {
    __half2 h = __floats2half2_rn(a, b);
    return *(unsigned*)&h;
}

// ---------------- kernels ----------------

// Fused setup: zero accumulators, int64 probe, W12 = W1@W2, c1 = W2^T b1.
__global__ void __launch_bounds__(256) k_w12z(const float* __restrict__ W1,
                                              const float* __restrict__ W2,
                                              const float* __restrict__ b1,
                                              const unsigned* __restrict__ w) {
    int i = blockIdx.x * 256 + threadIdx.x;
    if (i < NN) g_deg[i] = 0;
    if (i < NG * NC) g_pool[i] = 0.f;
    if (i < NG) { g_pu[i] = 0.f; g_pv[i] = 0.f; g_cnt[i] = 0; }

    int b = blockIdx.x;
    int warp = threadIdx.x >> 5, lane = threadIdx.x & 31;

    if (b == 0) {  // int64 probe: ids < 2^31 => int64 iff high words all 0
        __shared__ unsigned s;
        if (threadIdx.x == 0) s = 0u;
        __syncthreads();
        unsigned a = 0;
        for (int j = threadIdx.x; j < 4096; j += 256) a |= w[2 * j + 1];
        atomicOr(&s, a);
        __syncthreads();
        if (threadIdx.x == 0) g_is64 = (s == 0u) ? 1 : 0;
    } else if (b <= 160) {  // 1280 outputs, warp per output
        int idx = (b - 1) * 8 + warp;
        int k = idx / NC, c = idx - k * NC;
        float s = 0.f;
#pragma unroll
        for (int jj = 0; jj < 4; jj++) {
            int j = lane + jj * 32;
            s += W1[k * FD + j] * __ldg(W2 + j * NC + c);
        }
#pragma unroll
        for (int o = 16; o > 0; o >>= 1) s += __shfl_xor_sync(0xffffffffu, s, o);
        if (lane == 0) g_W12[k * RP + c] = s;
    } else if (b == 161) {
        if (warp < NC) {
            float s = 0.f;
#pragma unroll
            for (int jj = 0; jj < 4; jj++) {
                int j = lane + jj * 32;
                s += b1[j] * __ldg(W2 + j * NC + warp);
            }
#pragma unroll
            for (int o = 16; o > 0; o >>= 1) s += __shfl_xor_sync(0xffffffffu, s, o);
            if (lane == 0) g_c1[warp] = s;
        }
    }
}

// edge list -> packed int2 + in-degree count
__global__ void k_prep(const void* __restrict__ ei) {
    int e = blockIdx.x * 256 + threadIdx.x;
    if (e >= NE) return;
    int is64 = g_is64;
    int r = ld_idx(ei, e, is64);
    int c = ld_idx(ei, (long long)NE + e, is64);
    g_edges[e] = make_int2(r, c);
    atomicAdd(&g_deg[c], 1);
}

// z0 = dis*(X@W12) fp32 + fp16 mirror; zero a1. Warp-per-node.
__global__ void __launch_bounds__(256) k_gemm0(const float* __restrict__ x) {
    int lane = threadIdx.x & 31;
    int warpId = (blockIdx.x * 256 + threadIdx.x) >> 5;
    int nWarps = (gridDim.x * 256) >> 5;

    float w[4][NC];
#pragma unroll
    for (int kk = 0; kk < 4; kk++)
#pragma unroll
        for (int c = 0; c < NC; c++)
            w[kk][c] = g_W12[(lane * 4 + kk) * RP + c];

    const float4 zero4 = make_float4(0.f, 0.f, 0.f, 0.f);
    for (int n = warpId; n < NN; n += nWarps) {
        float4 xv = *(const float4*)(x + (size_t)n * FD + lane * 4);
        float acc[NC];
#pragma unroll
        for (int c = 0; c < NC; c++) acc[c] = 0.f;
#pragma unroll
        for (int kk = 0; kk < 4; kk++) {
            float xk = ((const float*)&xv)[kk];
#pragma unroll
            for (int c = 0; c < NC; c++) acc[c] += xk * w[kk][c];
        }
#pragma unroll
        for (int o = 16; o > 0; o >>= 1)
#pragma unroll
            for (int c = 0; c < NC; c++)
                acc[c] += __shfl_xor_sync(0xffffffffu, acc[c], o);

        float d = rsqrtf((float)g_deg[n] + 1.0f);
        float* p = g_z0 + (size_t)n * RP;
        float* q = g_a1 + (size_t)n * AP;
        __half* h = g_z0h + (size_t)n * HP;
        if (lane == 0)      *(float4*)p       = make_float4(acc[0]*d, acc[1]*d, acc[2]*d, acc[3]*d);
        else if (lane == 1) *(float4*)(p + 4) = make_float4(acc[4]*d, acc[5]*d, acc[6]*d, acc[7]*d);
        else if (lane == 2) *(float4*)(p + 8) = make_float4(acc[8]*d, acc[9]*d, d, 0.f);
        else if (lane == 3) *(uint4*)h = make_uint4(h2u(acc[0]*d, acc[1]*d), h2u(acc[2]*d, acc[3]*d),
                                                    h2u(acc[4]*d, acc[5]*d), h2u(acc[6]*d, acc[7]*d));
        else if (lane == 4) *(uint2*)(h + 8) = make_uint2(h2u(acc[8]*d, acc[9]*d), h2u(d, 0.f));
        else if (lane == 5) *(float4*)q       = zero4;
        else if (lane == 6) *(float4*)(q + 4) = zero4;
        else if (lane == 7) *(float4*)(q + 8) = zero4;
    }
}

// edge scatter 1: a1[c] += z0h[r] (fp16 gather, fp32 red). Persistent grid,
// 3 threads/edge: thread j loads 8B (4 halves) and reds one float4.
__global__ void __launch_bounds__(256) k_sc1() {
    int stride = gridDim.x * 256;
#pragma unroll 2
    for (int gid = blockIdx.x * 256 + threadIdx.x; gid < NE * 3; gid += stride) {
        int e = gid / 3;
        int j = gid - e * 3;
        int2 rc = g_edges[e];
        uint2 raw = *(const uint2*)(g_z0h + (size_t)rc.x * HP + j * 4);
        float2 f0 = __half22float2(*(__half2*)&raw.x);
        float2 f1 = __half22float2(*(__half2*)&raw.y);
        red_add_v4(g_a1 + (size_t)rc.y * AP + j * 4, make_float4(f0.x, f0.y, f1.x, f1.y));
    }
}

// mid: z1 = dc^2*(a1+z0); u = dc*t10; z1 s11=dc; fp16 mirror; zero a2.
__global__ void k_mid() {
    int n = blockIdx.x * 256 + threadIdx.x;
    if (n >= NN) return;
    const float* zp = g_z0 + (size_t)n * RP;
    const float* ap = g_a1 + (size_t)n * AP;
    float4 z0a = *(const float4*)zp,  z0b = *(const float4*)(zp + 4), z0c = *(const float4*)(zp + 8);
    float4 a0  = *(const float4*)ap,  a1  = *(const float4*)(ap + 4), a2  = *(const float4*)(ap + 8);
    float dc = z0c.z;
    float s2 = dc * dc;
    float t10 = a2.z + z0c.z;
    g_u[n] = dc * t10;
    float v0 = (a0.x+z0a.x)*s2, v1 = (a0.y+z0a.y)*s2, v2 = (a0.z+z0a.z)*s2, v3 = (a0.w+z0a.w)*s2;
    float v4 = (a1.x+z0b.x)*s2, v5 = (a1.y+z0b.y)*s2, v6 = (a1.z+z0b.z)*s2, v7 = (a1.w+z0b.w)*s2;
    float v8 = (a2.x+z0c.x)*s2, v9 = (a2.y+z0c.y)*s2, v10 = t10*s2;
    float* d = g_z1 + (size_t)n * RP;
    *(float4*)d       = make_float4(v0, v1, v2, v3);
    *(float4*)(d + 4) = make_float4(v4, v5, v6, v7);
    *(float4*)(d + 8) = make_float4(v8, v9, v10, dc);
    __half* h = g_z1h + (size_t)n * HP;
    *(uint4*)h       = make_uint4(h2u(v0,v1), h2u(v2,v3), h2u(v4,v5), h2u(v6,v7));
    *(uint2*)(h + 8) = make_uint2(h2u(v8,v9), h2u(v10, 0.f));
    const float4 zero4 = make_float4(0.f, 0.f, 0.f, 0.f);
    float* q = g_a2 + (size_t)n * AP;
    *(float4*)q = zero4; *(float4*)(q + 4) = zero4; *(float4*)(q + 8) = zero4;
}

// edge scatter 2: a2[c] += z1h[r]
__global__ void __launch_bounds__(256) k_sc2() {
    int stride = gridDim.x * 256;
#pragma unroll 2
    for (int gid = blockIdx.x * 256 + threadIdx.x; gid < NE * 3; gid += stride) {
        int e = gid / 3;
        int j = gid - e * 3;
        int2 rc = g_edges[e];
        uint2 raw = *(const uint2*)(g_z1h + (size_t)rc.x * HP + j * 4);
        float2 f0 = __half22float2(*(__half2*)&raw.x);
        float2 f1 = __half22float2(*(__half2*)&raw.y);
        red_add_v4(g_a2 + (size_t)rc.y * AP + j * 4, make_float4(f0.x, f0.y, f1.x, f1.y));
    }
}

// final node pass + fused pooling: y2 = dc*(a2+z1); v = dc*t10
__global__ void k_poolB(const void* __restrict__ batch) {
    __shared__ float sp[NG * NC];
    __shared__ float su[NG], sv[NG];
    __shared__ int sc[NG];
    int tid = threadIdx.x;
    for (int i = tid; i < NG * NC; i += 256) sp[i] = 0.f;
    if (tid < NG) { su[tid] = 0.f; sv[tid] = 0.f; sc[tid] = 0; }
    __syncthreads();

    int n = blockIdx.x * 256 + tid;
    if (n < NN) {
        const float* zp = g_z1 + (size_t)n * RP;
        const float* ap = g_a2 + (size_t)n * AP;
        float4 z0a = *(const float4*)zp,  z0b = *(const float4*)(zp + 4), z0c = *(const float4*)(zp + 8);
        float4 a0  = *(const float4*)ap,  a1  = *(const float4*)(ap + 4), a2  = *(const float4*)(ap + 8);
        float t[11] = {a0.x+z0a.x, a0.y+z0a.y, a0.z+z0a.z, a0.w+z0a.w,
                       a1.x+z0b.x, a1.y+z0b.y, a1.z+z0b.z, a1.w+z0b.w,
                       a2.x+z0c.x, a2.y+z0c.y, a2.z+z0c.z};
        float dc = z0c.w;                 // s11 = dis
        int g = ld_idx(batch, n, g_is64);
        atomicAdd(&sc[g], 1);
        atomicAdd(&su[g], g_u[n]);
        atomicAdd(&sv[g], dc * t[10]);
#pragma unroll
        for (int c = 0; c < NC; c++) atomicAdd(&sp[g * NC + c], dc * t[c]);
    }
    __syncthreads();
    for (int i = tid; i < NG * NC; i += 256)
        if (sp[i] != 0.f) atomicAdd(&g_pool[i], sp[i]);
    if (tid < NG) {
        if (sc[tid]) atomicAdd(&g_cnt[tid], sc[tid]);
        if (su[tid] != 0.f) atomicAdd(&g_pu[tid], su[tid]);
        if (sv[tid] != 0.f) atomicAdd(&g_pv[tid], sv[tid]);
    }
}

// combine rank-1 bias terms, mean, log_softmax -> [64,10]
__global__ void k_fin(const float* __restrict__ b2, float* __restrict__ out) {
    int g = threadIdx.x;
    if (g >= NG) return;
    float inv = 1.f / fmaxf((float)g_cnt[g], 1.f);
    float pu = g_pu[g], pv = g_pv[g];
    float v[NC];
    float m = -1e30f;
#pragma unroll
    for (int c = 0; c < NC; c++) {
        v[c] = (g_pool[g * NC + c] + pv * g_c1[c] + pu * __ldg(b2 + c)) * inv;
        m = fmaxf(m, v[c]);
    }
    float s = 0.f;
#pragma unroll
    for (int c = 0; c < NC; c++) s += expf(v[c] - m);
    float l = logf(s);
#pragma unroll
    for (int c = 0; c < NC; c++) out[g * NC + c] = v[c] - m - l;
}

// ---------------- launch ----------------
extern "C" void kernel_launch(void* const* d_in, const int* in_sizes, int n_in,
                              void* d_out, int out_size) {
    const float* x = nullptr;
    const void* ei = nullptr;
    const void* batch = nullptr;
    const float *W1 = nullptr, *b1 = nullptr, *W2 = nullptr, *b2 = nullptr;

    for (int i = 0; i < n_in; i++) {
        switch (in_sizes[i]) {
            case 12800000: x = (const float*)d_in[i]; break;
            case 3200000:  ei = d_in[i]; break;
            case 100000:   batch = d_in[i]; break;
            case 16384:    W1 = (const float*)d_in[i]; break;
            case 128:      b1 = (const float*)d_in[i]; break;
            case 1280:     W2 = (const float*)d_in[i]; break;
            case 10:       b2 = (const float*)d_in[i]; break;
            default: break;
        }
    }
    float* out = (float*)d_out;
    const int NB_E = (NE + 255) / 256;

    k_w12z<<<NB_N, 256>>>(W1, W2, b1, (const unsigned*)ei);
    k_prep<<<NB_E, 256>>>(ei);
    k_gemm0<<<1184, 256>>>(x);
    k_sc1<<<1184, 256>>>();          // slot 4 -> profiled; persistent grid
    k_mid<<<NB_N, 256>>>();
    k_sc2<<<1184, 256>>>();
    k_poolB<<<NB_N, 256>>>(batch);
    k_fin<<<1, 64>>>(b2, out);
}

// round 12
// speedup vs baseline: 1.0428x; 1.0428x over previous
#include <cuda_runtime.h>
#include <cstdint>
#include <cstddef>

#define NN 100000
#define NE 1600000
#define FD 128
#define NC 10
#define RP 12          // row stride floats: 10 feats + scalar chan + dis (48B)
#define NG 64
#define NBLK 444       // 148 SMs x 3 blocks -- co-resident by __launch_bounds__
#define NTHR 256
#define GSZ (NBLK * NTHR)

// ---------------- device scratch (allocation-free rule) ----------------
__device__ __align__(128) float g_z0[(size_t)NN * RP];  // dr*y0 row, s10=dr
__device__ __align__(128) float g_a1[(size_t)NN * RP];  // edge acc pass 1
__device__ __align__(128) float g_z1[(size_t)NN * RP];  // s10=t10*s2, s11=dc
__device__ __align__(128) float g_a2[(size_t)NN * RP];  // edge acc pass 2
__device__ int2  g_edges[NE];
__device__ float g_u[NN];
__device__ int   g_deg[NN];
__device__ float g_W12[FD * RP];
__device__ float g_c1[NC];
__device__ float g_pool[NG * NC];
__device__ float g_pu[NG];
__device__ float g_pv[NG];
__device__ int   g_cnt[NG];
__device__ int   g_is64;
__device__ int   g_count;          // barrier arrival counter (self-resetting)
__device__ volatile int g_gen;     // barrier generation (monotone across replays)

// ---------------- helpers ----------------
__device__ __forceinline__ int ld_idx(const void* p, long long i, int is64) {
    if (is64) return (int)((const long long*)p)[i];
    return ((const int*)p)[i];
}
__device__ __forceinline__ void red_add_v4(float* p, float4 v) {
    asm volatile("red.global.add.v4.f32 [%0], {%1,%2,%3,%4};"
                 :: "l"(p), "f"(v.x), "f"(v.y), "f"(v.z), "f"(v.w)
                 : "memory");
}

// software grid barrier. All NBLK blocks are co-resident (launch_bounds), so
// spin cannot deadlock. threadfence on both sides: release (drain my STG/RED
// to L2) and acquire (gpu-scope fence -> CCTL.IVALL -> invalidate my L1D so
// peer writes are visible; replaces the per-launch L1 flush).
__device__ __forceinline__ void gsync() {
    __syncthreads();
    if (threadIdx.x == 0) {
        int gen = g_gen;
        __threadfence();
        if (atomicAdd(&g_count, 1) == NBLK - 1) {
            g_count = 0;
            __threadfence();
            g_gen = gen + 1;
        } else {
            while (g_gen == gen) __nanosleep(64);
            __threadfence();
        }
    }
    __syncthreads();
}

// ---------------- the whole pipeline, one kernel ----------------
extern "C" __global__ void __launch_bounds__(NTHR, 3)
k_all(const float* __restrict__ x, const void* __restrict__ ei,
      const void* __restrict__ batch,
      const float* __restrict__ W1, const float* __restrict__ b1,
      const float* __restrict__ W2, const float* __restrict__ b2,
      float* __restrict__ out)
{
    __shared__ float sp[NG * NC];
    __shared__ float su[NG], sv[NG];
    __shared__ int sc_[NG];
    __shared__ unsigned sprobe;

    int tid = threadIdx.x, bid = blockIdx.x;
    int gtid = bid * NTHR + tid;
    int warp = tid >> 5, lane = tid & 31;

    // ===== phase 0: zero accumulators, W12 = W1@W2, c1 = W2^T b1, is64 probe
    for (int i = gtid; i < NN; i += GSZ) g_deg[i] = 0;
    if (gtid < NG * NC) g_pool[gtid] = 0.f;
    if (gtid < NG) { g_pu[gtid] = 0.f; g_pv[gtid] = 0.f; g_cnt[gtid] = 0; }

    if (bid < 160) {                 // 1280 W12 outputs, warp per output
        int idx = bid * 8 + warp;
        int k = idx / NC, c = idx - k * NC;
        float s = 0.f;
#pragma unroll
        for (int jj = 0; jj < 4; jj++) {
            int j = lane + jj * 32;
            s += W1[k * FD + j] * __ldg(W2 + j * NC + c);
        }
#pragma unroll
        for (int o = 16; o > 0; o >>= 1) s += __shfl_xor_sync(0xffffffffu, s, o);
        if (lane == 0) g_W12[k * RP + c] = s;
    } else if (bid == 160) {         // c1
        if (warp < NC) {
            float s = 0.f;
#pragma unroll
            for (int jj = 0; jj < 4; jj++) {
                int j = lane + jj * 32;
                s += b1[j] * __ldg(W2 + j * NC + warp);
            }
#pragma unroll
            for (int o = 16; o > 0; o >>= 1) s += __shfl_xor_sync(0xffffffffu, s, o);
            if (lane == 0) g_c1[warp] = s;
        }
    } else if (bid == 161) {         // int64 probe: ids < 2^31 => hi words 0
        const unsigned* w = (const unsigned*)ei;
        if (tid == 0) sprobe = 0u;
        __syncthreads();
        unsigned a = 0;
        for (int j = tid; j < 4096; j += NTHR) a |= w[2 * j + 1];
        atomicOr(&sprobe, a);
        __syncthreads();
        if (tid == 0) g_is64 = (sprobe == 0u) ? 1 : 0;
    }
    gsync();

    // ===== phase 1: edge repack + in-degree (2 edges/thread, vector loads)
    int is64 = g_is64;
    for (int t = gtid; t < NE / 2; t += GSZ) {
        int r0, r1, c0, c1v;
        if (is64) {
            longlong2 rr = ((const longlong2*)ei)[t];
            longlong2 cc = ((const longlong2*)ei)[NE / 2 + t];
            r0 = (int)rr.x; r1 = (int)rr.y; c0 = (int)cc.x; c1v = (int)cc.y;
        } else {
            int2 rr = ((const int2*)ei)[t];
            int2 cc = ((const int2*)ei)[NE / 2 + t];
            r0 = rr.x; r1 = rr.y; c0 = cc.x; c1v = cc.y;
        }
        *(int4*)&g_edges[t * 2] = make_int4(r0, c0, r1, c1v);
        atomicAdd(&g_deg[c0], 1);
        atomicAdd(&g_deg[c1v], 1);
    }
    gsync();

    // ===== phase 2: z0 = dis*(X@W12), s10 = dis; zero a1. Warp-per-node.
    {
        float w[4][NC];
#pragma unroll
        for (int kk = 0; kk < 4; kk++)
#pragma unroll
            for (int c = 0; c < NC; c++)
                w[kk][c] = g_W12[(lane * 4 + kk) * RP + c];

        const float4 zero4 = make_float4(0.f, 0.f, 0.f, 0.f);
        int warpId = gtid >> 5;
        const int nW = GSZ >> 5;
        for (int n = warpId; n < NN; n += nW) {
            float4 xv = *(const float4*)(x + (size_t)n * FD + lane * 4);
            float acc[NC];
#pragma unroll
            for (int c = 0; c < NC; c++) acc[c] = 0.f;
#pragma unroll
            for (int kk = 0; kk < 4; kk++) {
                float xk = ((const float*)&xv)[kk];
#pragma unroll
                for (int c = 0; c < NC; c++) acc[c] += xk * w[kk][c];
            }
#pragma unroll
            for (int o = 16; o > 0; o >>= 1)
#pragma unroll
                for (int c = 0; c < NC; c++)
                    acc[c] += __shfl_xor_sync(0xffffffffu, acc[c], o);

            float d = rsqrtf((float)g_deg[n] + 1.0f);
            float* p = g_z0 + (size_t)n * RP;
            float* q = g_a1 + (size_t)n * RP;
            if (lane == 0)      *(float4*)p       = make_float4(acc[0]*d, acc[1]*d, acc[2]*d, acc[3]*d);
            else if (lane == 1) *(float4*)(p + 4) = make_float4(acc[4]*d, acc[5]*d, acc[6]*d, acc[7]*d);
            else if (lane == 2) *(float4*)(p + 8) = make_float4(acc[8]*d, acc[9]*d, d, 0.f);
            else if (lane == 4) *(float4*)q       = zero4;
            else if (lane == 5) *(float4*)(q + 4) = zero4;
            else if (lane == 6) *(float4*)(q + 8) = zero4;
        }
    }
    gsync();

    // ===== phase 3: edge scatter 1: a1[c] += z0[r] (3 threads/edge)
    for (int gid = gtid; gid < NE * 3; gid += GSZ) {
        int e = gid / 3;
        int j = gid - e * 3;
        int2 rc = g_edges[e];
        float4 v = *(const float4*)(g_z0 + (size_t)rc.x * RP + j * 4);
        red_add_v4(g_a1 + (size_t)rc.y * RP + j * 4, v);
    }
    gsync();

    // ===== phase 4: z1 = dc^2*(a1+z0); u = dc*t10; z1 s11 = dc; zero a2
    for (int n = gtid; n < NN; n += GSZ) {
        const float* zp = g_z0 + (size_t)n * RP;
        const float* ap = g_a1 + (size_t)n * RP;
        float4 z0a = *(const float4*)zp,  z0b = *(const float4*)(zp + 4), z0c = *(const float4*)(zp + 8);
        float4 a0  = *(const float4*)ap,  a1  = *(const float4*)(ap + 4), a2  = *(const float4*)(ap + 8);
        float dc = z0c.z;
        float s2 = dc * dc;
        float t10 = a2.z + z0c.z;
        g_u[n] = dc * t10;
        float* d = g_z1 + (size_t)n * RP;
        *(float4*)d       = make_float4((a0.x+z0a.x)*s2, (a0.y+z0a.y)*s2, (a0.z+z0a.z)*s2, (a0.w+z0a.w)*s2);
        *(float4*)(d + 4) = make_float4((a1.x+z0b.x)*s2, (a1.y+z0b.y)*s2, (a1.z+z0b.z)*s2, (a1.w+z0b.w)*s2);
        *(float4*)(d + 8) = make_float4((a2.x+z0c.x)*s2, (a2.y+z0c.y)*s2, t10*s2, dc);
        const float4 zero4 = make_float4(0.f, 0.f, 0.f, 0.f);
        float* q = g_a2 + (size_t)n * RP;
        *(float4*)q = zero4; *(float4*)(q + 4) = zero4; *(float4*)(q + 8) = zero4;
    }
    gsync();

    // ===== phase 5: edge scatter 2: a2[c] += z1[r]
    for (int gid = gtid; gid < NE * 3; gid += GSZ) {
        int e = gid / 3;
        int j = gid - e * 3;
        int2 rc = g_edges[e];
        float4 v = *(const float4*)(g_z1 + (size_t)rc.x * RP + j * 4);
        red_add_v4(g_a2 + (size_t)rc.y * RP + j * 4, v);
    }
    gsync();

    // ===== phase 6: final node pass + pooling (shared combine, then global)
    for (int i = tid; i < NG * NC; i += NTHR) sp[i] = 0.f;
    if (tid < NG) { su[tid] = 0.f; sv[tid] = 0.f; sc_[tid] = 0; }
    __syncthreads();
    for (int n = gtid; n < NN; n += GSZ) {
        const float* zp = g_z1 + (size_t)n * RP;
        const float* ap = g_a2 + (size_t)n * RP;
        float4 z0a = *(const float4*)zp,  z0b = *(const float4*)(zp + 4), z0c = *(const float4*)(zp + 8);
        float4 a0  = *(const float4*)ap,  a1  = *(const float4*)(ap + 4), a2  = *(const float4*)(ap + 8);
        float t[11] = {a0.x+z0a.x, a0.y+z0a.y, a0.z+z0a.z, a0.w+z0a.w,
                       a1.x+z0b.x, a1.y+z0b.y, a1.z+z0b.z, a1.w+z0b.w,
                       a2.x+z0c.x, a2.y+z0c.y, a2.z+z0c.z};
        float dc = z0c.w;             // s11 = dis (from phase 4)
        int g = ld_idx(batch, n, is64);
        atomicAdd(&sc_[g], 1);
        atomicAdd(&su[g], g_u[n]);
        atomicAdd(&sv[g], dc * t[10]);
#pragma unroll
        for (int c = 0; c < NC; c++) atomicAdd(&sp[g * NC + c], dc * t[c]);
    }
    __syncthreads();
    for (int i = tid; i < NG * NC; i += NTHR)
        if (sp[i] != 0.f) atomicAdd(&g_pool[i], sp[i]);
    if (tid < NG) {
        if (sc_[tid]) atomicAdd(&g_cnt[tid], sc_[tid]);
        if (su[tid] != 0.f) atomicAdd(&g_pu[tid], su[tid]);
        if (sv[tid] != 0.f) atomicAdd(&g_pv[tid], sv[tid]);
    }
    gsync();

    // ===== phase 7: rank-1 bias combine + mean + log_softmax (block 0)
    if (bid == 0 && tid < NG) {
        int g = tid;
        float inv = 1.f / fmaxf((float)g_cnt[g], 1.f);
        float pu = g_pu[g], pv = g_pv[g];
        float v[NC];
        float m = -1e30f;
#pragma unroll
        for (int c = 0; c < NC; c++) {
            v[c] = (g_pool[g * NC + c] + pv * g_c1[c] + pu * __ldg(b2 + c)) * inv;
            m = fmaxf(m, v[c]);
        }
        float s = 0.f;
#pragma unroll
        for (int c = 0; c < NC; c++) s += expf(v[c] - m);
        float l = logf(s);
#pragma unroll
        for (int c = 0; c < NC; c++) out[g * NC + c] = v[c] - m - l;
    }
}

// ---------------- launch ----------------
extern "C" void kernel_launch(void* const* d_in, const int* in_sizes, int n_in,
                              void* d_out, int out_size) {
    const float* x = nullptr;
    const void* ei = nullptr;
    const void* batch = nullptr;
    const float *W1 = nullptr, *b1 = nullptr, *W2 = nullptr, *b2 = nullptr;

    for (int i = 0; i < n_in; i++) {
        switch (in_sizes[i]) {
            case 12800000: x = (const float*)d_in[i]; break;
            case 3200000:  ei = d_in[i]; break;
            case 100000:   batch = d_in[i]; break;
            case 16384:    W1 = (const float*)d_in[i]; break;
            case 128:      b1 = (const float*)d_in[i]; break;
            case 1280:     W2 = (const float*)d_in[i]; break;
            case 10:       b2 = (const float*)d_in[i]; break;
            default: break;
        }
    }
    k_all<<<NBLK, NTHR>>>(x, ei, batch, W1, b1, W2, b2, (float*)d_out);
}